// round 1
// baseline (speedup 1.0000x reference)
#include <cuda_runtime.h>
#include <math.h>

// ---------------------------------------------------------------------------
// Problem constants
// ---------------------------------------------------------------------------
#define EPSLN 1e-5f
#define DT    0.01f
#define CDIM  256
#define BDIM  8
#define NTOK  256
#define HEADS 8
#define HD    32
#define ROWS  (BDIM * NTOK)   // 2048

// ODE tiling
#define MROW 16   // rows per CTA
#define MP   20   // padded row-stride in transposed smem buffers

// ---------------------------------------------------------------------------
// Scratch (device globals: no allocation allowed)
// ---------------------------------------------------------------------------
__device__ float g_qbuf[3 * BDIM * HEADS * NTOK * HD]; // [3][B][H][N][hd]
__device__ float g_attnout[ROWS * CDIM];               // attention concat [B*N][C]
__device__ float g_x1[ROWS * CDIM];                    // x1 = LN(x + attn)
__device__ float g_ode[ROWS * CDIM];                   // ODE output at lead time

// ---------------------------------------------------------------------------
// K1: qkv = x @ wqkv + bqkv, scattered into [3][B][H][N][hd]
// grid (64 rowblocks, 3 colblocks), 256 threads
// ---------------------------------------------------------------------------
__global__ void qkv_kernel(const float* __restrict__ x,
                           const float* __restrict__ wqkv,
                           const float* __restrict__ bqkv) {
    __shared__ __align__(16) float As[CDIM * 36]; // x tile transposed [k][m], pad 36
    int tid = threadIdx.x, cg = tid & 31, rg = tid >> 5;
    int r0 = blockIdx.x * 32;
    int cb = blockIdx.y; // 0=q,1=k,2=v (256 cols each)

    for (int idx = tid; idx < 32 * CDIM; idx += 256) {
        int c = idx & 255, m = idx >> 8;
        As[c * 36 + m] = x[(r0 + m) * CDIM + c];
    }
    __syncthreads();

    float acc[4][8];
#pragma unroll
    for (int j = 0; j < 8; j++) {
        float bv = bqkv[cb * 256 + cg + 32 * j];
#pragma unroll
        for (int mm = 0; mm < 4; mm++) acc[mm][j] = bv;
    }
    int m0 = rg * 4;
    const float* wp = wqkv + cb * 256 + cg;
#pragma unroll 4
    for (int k = 0; k < CDIM; k++) {
        float4 av = *(const float4*)(As + k * 36 + m0);
#pragma unroll
        for (int j = 0; j < 8; j++) {
            float w = wp[k * 768 + 32 * j];
            acc[0][j] = fmaf(av.x, w, acc[0][j]);
            acc[1][j] = fmaf(av.y, w, acc[1][j]);
            acc[2][j] = fmaf(av.z, w, acc[2][j]);
            acc[3][j] = fmaf(av.w, w, acc[3][j]);
        }
    }
#pragma unroll
    for (int mm = 0; mm < 4; mm++) {
        int r = r0 + m0 + mm;
        int b = r >> 8, n = r & 255;
#pragma unroll
        for (int j = 0; j < 8; j++) {
            int cl = cg + 32 * j;       // local col 0..255
            int h = cl >> 5, d = cl & 31;
            g_qbuf[(((cb * BDIM + b) * HEADS + h) * NTOK + n) * HD + d] = acc[mm][j];
        }
    }
}

// ---------------------------------------------------------------------------
// K2: per-(b,h) softmax attention. grid 64, 256 threads (8 warps x 32 rows each)
// ---------------------------------------------------------------------------
#define ATTN_SMEM ((3 * 256 * 33 + 8 * 256) * 4)

__global__ void attn_kernel() {
    extern __shared__ float sm[];
    float* qs = sm;                  // [256][33]
    float* ks = qs + 256 * 33;
    float* vs = ks + 256 * 33;
    float* prob = vs + 256 * 33;     // [8 warps][256]

    int tid = threadIdx.x, lane = tid & 31, w = tid >> 5;
    int bh = blockIdx.x, b = bh >> 3, h = bh & 7;
    const float scale = 0.17677669529663687f; // 1/sqrt(32)

    const float* qg = g_qbuf + ((0 * BDIM + b) * HEADS + h) * NTOK * HD;
    const float* kg = g_qbuf + ((1 * BDIM + b) * HEADS + h) * NTOK * HD;
    const float* vg = g_qbuf + ((2 * BDIM + b) * HEADS + h) * NTOK * HD;
    for (int idx = tid; idx < NTOK * HD; idx += 256) {
        int n = idx >> 5, d = idx & 31;
        qs[n * 33 + d] = qg[idx] * scale;
        ks[n * 33 + d] = kg[idx];
        vs[n * 33 + d] = vg[idx];
    }
    __syncthreads();

    for (int n = w; n < NTOK; n += 8) {
        float s[8];
#pragma unroll
        for (int u = 0; u < 8; u++) {
            int j = lane + 32 * u;
            float a = 0.f;
#pragma unroll 8
            for (int d = 0; d < HD; d++) a = fmaf(qs[n * 33 + d], ks[j * 33 + d], a);
            s[u] = a;
        }
        float mx = s[0];
#pragma unroll
        for (int u = 1; u < 8; u++) mx = fmaxf(mx, s[u]);
#pragma unroll
        for (int o = 16; o > 0; o >>= 1) mx = fmaxf(mx, __shfl_xor_sync(0xffffffffu, mx, o));
        float sum = 0.f;
#pragma unroll
        for (int u = 0; u < 8; u++) { s[u] = __expf(s[u] - mx); sum += s[u]; }
#pragma unroll
        for (int o = 16; o > 0; o >>= 1) sum += __shfl_xor_sync(0xffffffffu, sum, o);
        float inv = 1.f / sum;
#pragma unroll
        for (int u = 0; u < 8; u++) prob[w * 256 + lane + 32 * u] = s[u] * inv;
        __syncwarp();
        // po_d = sum_j prob[j] * v[j][d]
        float acc = 0.f;
#pragma unroll 8
        for (int j = 0; j < NTOK; j++) acc = fmaf(prob[w * 256 + j], vs[j * 33 + lane], acc);
        g_attnout[(b * NTOK + n) * CDIM + h * HD + lane] = acc;
        __syncwarp();
    }
}

// ---------------------------------------------------------------------------
// K3: x1 = LN(x + attnout @ wo + bo; g1,b1). grid 64, 256 threads
// ---------------------------------------------------------------------------
__global__ void proj_ln_kernel(const float* __restrict__ x,
                               const float* __restrict__ wo,
                               const float* __restrict__ bo,
                               const float* __restrict__ g1,
                               const float* __restrict__ b1) {
    __shared__ __align__(16) float As[CDIM * 36];
    int tid = threadIdx.x, cg = tid & 31, rg = tid >> 5;
    int r0 = blockIdx.x * 32;
    for (int idx = tid; idx < 32 * CDIM; idx += 256) {
        int c = idx & 255, m = idx >> 8;
        As[c * 36 + m] = g_attnout[(r0 + m) * CDIM + c];
    }
    __syncthreads();

    float acc[4][8];
#pragma unroll
    for (int j = 0; j < 8; j++) {
        float bv = bo[cg + 32 * j];
#pragma unroll
        for (int mm = 0; mm < 4; mm++) acc[mm][j] = bv;
    }
    int m0 = rg * 4;
    const float* wp = wo + cg;
#pragma unroll 4
    for (int k = 0; k < CDIM; k++) {
        float4 av = *(const float4*)(As + k * 36 + m0);
#pragma unroll
        for (int j = 0; j < 8; j++) {
            float w = wp[k * CDIM + 32 * j];
            acc[0][j] = fmaf(av.x, w, acc[0][j]);
            acc[1][j] = fmaf(av.y, w, acc[1][j]);
            acc[2][j] = fmaf(av.z, w, acc[2][j]);
            acc[3][j] = fmaf(av.w, w, acc[3][j]);
        }
    }
    // residual + LN (warp covers all 256 cols of its 4 rows)
#pragma unroll
    for (int mm = 0; mm < 4; mm++) {
        int r = r0 + m0 + mm;
#pragma unroll
        for (int j = 0; j < 8; j++) acc[mm][j] += x[r * CDIM + cg + 32 * j];
        float ls = 0.f, lq = 0.f;
#pragma unroll
        for (int j = 0; j < 8; j++) { ls += acc[mm][j]; lq += acc[mm][j] * acc[mm][j]; }
#pragma unroll
        for (int o = 16; o > 0; o >>= 1) {
            ls += __shfl_xor_sync(0xffffffffu, ls, o);
            lq += __shfl_xor_sync(0xffffffffu, lq, o);
        }
        float mean = ls * (1.f / 256.f);
        float var  = lq * (1.f / 256.f) - mean * mean;
        float rstd = rsqrtf(var + EPSLN);
#pragma unroll
        for (int j = 0; j < 8; j++) {
            int c = cg + 32 * j;
            g_x1[r * CDIM + c] = (acc[mm][j] - mean) * rstd * g1[c] + b1[c];
        }
    }
}

// ---------------------------------------------------------------------------
// K4: persistent ODE kernel. 128 CTAs x 128 threads; 16 rows/CTA, all RK4
// state in SMEM (transposed [C][MP] layout). Per-batch early exit at lead_time.
// ---------------------------------------------------------------------------
#define ODE_SMEM (6 * CDIM * MP * 4)

template <int FINAL>
__device__ __forceinline__ void feval(
    const float* __restrict__ arg, float* __restrict__ out,
    const float* __restrict__ k1s, const float* __restrict__ k2s,
    const float* __restrict__ k3s, float* __restrict__ h1s,
    const float* __restrict__ wl1, const float* __restrict__ bl1,
    const float* __restrict__ wl2, const float* __restrict__ bl2,
    const float* __restrict__ gn, const float* __restrict__ bn,
    int cg, int m0) {
    float a0[8], a1[8], a2[8], a3[8];
    // ---- GEMM1: h1 = relu(arg @ wl1 + bl1) ----
#pragma unroll
    for (int j = 0; j < 8; j++) {
        float bv = bl1[cg + 32 * j];
        a0[j] = bv; a1[j] = bv; a2[j] = bv; a3[j] = bv;
    }
    {
        const float* wp = wl1 + cg;
#pragma unroll 4
        for (int k = 0; k < CDIM; k++) {
            float4 av = *(const float4*)(arg + k * MP + m0);
#pragma unroll
            for (int j = 0; j < 8; j++) {
                float w = __ldg(wp + k * CDIM + 32 * j);
                a0[j] = fmaf(av.x, w, a0[j]);
                a1[j] = fmaf(av.y, w, a1[j]);
                a2[j] = fmaf(av.z, w, a2[j]);
                a3[j] = fmaf(av.w, w, a3[j]);
            }
        }
    }
#pragma unroll
    for (int j = 0; j < 8; j++) {
        int c = cg + 32 * j;
        h1s[c * MP + m0 + 0] = fmaxf(a0[j], 0.f);
        h1s[c * MP + m0 + 1] = fmaxf(a1[j], 0.f);
        h1s[c * MP + m0 + 2] = fmaxf(a2[j], 0.f);
        h1s[c * MP + m0 + 3] = fmaxf(a3[j], 0.f);
    }
    __syncthreads();
    // ---- GEMM2: h2 = h1 @ wl2 + bl2 ----
#pragma unroll
    for (int j = 0; j < 8; j++) {
        float bv = bl2[cg + 32 * j];
        a0[j] = bv; a1[j] = bv; a2[j] = bv; a3[j] = bv;
    }
    {
        const float* wp = wl2 + cg;
#pragma unroll 4
        for (int k = 0; k < CDIM; k++) {
            float4 hv = *(const float4*)(h1s + k * MP + m0);
#pragma unroll
            for (int j = 0; j < 8; j++) {
                float w = __ldg(wp + k * CDIM + 32 * j);
                a0[j] = fmaf(hv.x, w, a0[j]);
                a1[j] = fmaf(hv.y, w, a1[j]);
                a2[j] = fmaf(hv.z, w, a2[j]);
                a3[j] = fmaf(hv.w, w, a3[j]);
            }
        }
    }
    // ---- residual + LN, then emit k (or fuse RK4 combine on final eval) ----
#pragma unroll
    for (int j = 0; j < 8; j++) {
        int c = cg + 32 * j;
        a0[j] += arg[c * MP + m0 + 0];
        a1[j] += arg[c * MP + m0 + 1];
        a2[j] += arg[c * MP + m0 + 2];
        a3[j] += arg[c * MP + m0 + 3];
    }
    auto lnrow = [&](float* a, int mm) {
        float ls = 0.f, lq = 0.f;
#pragma unroll
        for (int j = 0; j < 8; j++) { ls += a[j]; lq += a[j] * a[j]; }
#pragma unroll
        for (int o = 16; o > 0; o >>= 1) {
            ls += __shfl_xor_sync(0xffffffffu, ls, o);
            lq += __shfl_xor_sync(0xffffffffu, lq, o);
        }
        float mean = ls * (1.f / 256.f);
        float var  = lq * (1.f / 256.f) - mean * mean;
        float rstd = rsqrtf(var + EPSLN);
#pragma unroll
        for (int j = 0; j < 8; j++) {
            int c = cg + 32 * j;
            float kv = (a[j] - mean) * rstd * gn[c] + bn[c];
            int o = c * MP + m0 + mm;
            if (FINAL) {
                out[o] = out[o] + DT * 0.125f * (k1s[o] + 3.f * (k2s[o] + k3s[o]) + kv);
            } else {
                out[o] = kv;
            }
        }
    };
    lnrow(a0, 0); lnrow(a1, 1); lnrow(a2, 2); lnrow(a3, 3);
    __syncthreads();
}

__global__ void __launch_bounds__(128, 1)
ode_kernel(const int* __restrict__ lead_times, const int* __restrict__ nsp,
           const float* __restrict__ wl1, const float* __restrict__ bl1,
           const float* __restrict__ wl2, const float* __restrict__ bl2,
           const float* __restrict__ gn, const float* __restrict__ bn) {
    extern __shared__ __align__(16) float sm[];
    float* ys   = sm;
    float* k1s  = sm + 1 * CDIM * MP;
    float* k2s  = sm + 2 * CDIM * MP;
    float* k3s  = sm + 3 * CDIM * MP;
    float* args = sm + 4 * CDIM * MP;
    float* h1s  = sm + 5 * CDIM * MP;

    int tid = threadIdx.x, cg = tid & 31, rg = tid >> 5, m0 = rg * 4;
    int r0 = blockIdx.x * MROW;
    int steps = lead_times[r0 >> 8];
    int ns = nsp ? nsp[0] : 50;
    if (steps > ns) steps = ns;
    if (steps < 0) steps = 0;

    for (int idx = tid; idx < MROW * CDIM; idx += 128) {
        int c = idx & 255, m = idx >> 8;
        ys[c * MP + m] = g_x1[(r0 + m) * CDIM + c];
    }
    __syncthreads();

    for (int s = 0; s < steps; s++) {
        // k1 = f(y)
        feval<0>(ys, k1s, nullptr, nullptr, nullptr, h1s, wl1, bl1, wl2, bl2, gn, bn, cg, m0);
        // arg = y + dt/3 * k1
        for (int idx = tid; idx < MROW * CDIM; idx += 128) {
            int m = idx & 15, c = idx >> 4, o = c * MP + m;
            args[o] = ys[o] + (DT * (1.f / 3.f)) * k1s[o];
        }
        __syncthreads();
        // k2 = f(arg)
        feval<0>(args, k2s, nullptr, nullptr, nullptr, h1s, wl1, bl1, wl2, bl2, gn, bn, cg, m0);
        // arg = y + dt*(k2 - k1/3)
        for (int idx = tid; idx < MROW * CDIM; idx += 128) {
            int m = idx & 15, c = idx >> 4, o = c * MP + m;
            args[o] = ys[o] + DT * (k2s[o] - (1.f / 3.f) * k1s[o]);
        }
        __syncthreads();
        // k3 = f(arg)
        feval<0>(args, k3s, nullptr, nullptr, nullptr, h1s, wl1, bl1, wl2, bl2, gn, bn, cg, m0);
        // arg = y + dt*(k1 - k2 + k3)
        for (int idx = tid; idx < MROW * CDIM; idx += 128) {
            int m = idx & 15, c = idx >> 4, o = c * MP + m;
            args[o] = ys[o] + DT * (k1s[o] - k2s[o] + k3s[o]);
        }
        __syncthreads();
        // k4 = f(arg), fused: y += dt/8 * (k1 + 3(k2+k3) + k4)
        feval<1>(args, ys, k1s, k2s, k3s, h1s, wl1, bl1, wl2, bl2, gn, bn, cg, m0);
    }

    for (int idx = tid; idx < MROW * CDIM; idx += 128) {
        int c = idx & 255, m = idx >> 8;
        g_ode[(r0 + m) * CDIM + c] = ys[c * MP + m];
    }
}

// ---------------------------------------------------------------------------
// K5: out = LN(x1 + ode; g2,b2). grid 256, 256 threads (warp per row)
// ---------------------------------------------------------------------------
__global__ void final_ln_kernel(const float* __restrict__ g2,
                                const float* __restrict__ b2,
                                float* __restrict__ out) {
    int tid = threadIdx.x, lane = tid & 31, w = tid >> 5;
    int r = blockIdx.x * 8 + w;
    float v[8], ls = 0.f, lq = 0.f;
#pragma unroll
    for (int u = 0; u < 8; u++) {
        int c = lane + 32 * u;
        float t = g_x1[r * CDIM + c] + g_ode[r * CDIM + c];
        v[u] = t; ls += t; lq += t * t;
    }
#pragma unroll
    for (int o = 16; o > 0; o >>= 1) {
        ls += __shfl_xor_sync(0xffffffffu, ls, o);
        lq += __shfl_xor_sync(0xffffffffu, lq, o);
    }
    float mean = ls * (1.f / 256.f);
    float var  = lq * (1.f / 256.f) - mean * mean;
    float rstd = rsqrtf(var + EPSLN);
#pragma unroll
    for (int u = 0; u < 8; u++) {
        int c = lane + 32 * u;
        out[r * CDIM + c] = (v[u] - mean) * rstd * g2[c] + b2[c];
    }
}

// ---------------------------------------------------------------------------
// Launch
// ---------------------------------------------------------------------------
extern "C" void kernel_launch(void* const* d_in, const int* in_sizes, int n_in,
                              void* d_out, int out_size) {
    const float* x    = (const float*)d_in[0];
    const float* wqkv = (const float*)d_in[1];
    const float* bqkv = (const float*)d_in[2];
    const float* wo   = (const float*)d_in[3];
    const float* bo   = (const float*)d_in[4];
    const float* g1   = (const float*)d_in[5];
    const float* b1   = (const float*)d_in[6];
    const float* g2   = (const float*)d_in[7];
    const float* b2   = (const float*)d_in[8];
    const float* wl1  = (const float*)d_in[9];
    const float* bl1  = (const float*)d_in[10];
    const float* wl2  = (const float*)d_in[11];
    const float* bl2  = (const float*)d_in[12];
    const float* gn   = (const float*)d_in[13];
    const float* bn   = (const float*)d_in[14];
    const int* lead   = (const int*)d_in[15];
    const int* nsteps = (n_in > 16) ? (const int*)d_in[16] : nullptr;
    float* out = (float*)d_out;

    cudaFuncSetAttribute(attn_kernel, cudaFuncAttributeMaxDynamicSharedMemorySize, ATTN_SMEM);
    cudaFuncSetAttribute(ode_kernel, cudaFuncAttributeMaxDynamicSharedMemorySize, ODE_SMEM);

    qkv_kernel<<<dim3(64, 3), 256>>>(x, wqkv, bqkv);
    attn_kernel<<<64, 256, ATTN_SMEM>>>();
    proj_ln_kernel<<<64, 256>>>(x, wo, bo, g1, b1);
    ode_kernel<<<128, 128, ODE_SMEM>>>(lead, nsteps, wl1, bl1, wl2, bl2, gn, bn);
    final_ln_kernel<<<256, 256>>>(g2, b2, out);
}

// round 3
// speedup vs baseline: 2.2901x; 2.2901x over previous
#include <cuda_runtime.h>
#include <math.h>
#include <stdint.h>

// ---------------------------------------------------------------------------
// Problem constants
// ---------------------------------------------------------------------------
#define EPSLN 1e-5f
#define DT    0.01f
#define CDIM  256
#define BDIM  8
#define NTOK  256
#define HEADS 8
#define HD    32
#define ROWS  (BDIM * NTOK)   // 2048

// ODE tiling
#define MROW 16          // rows per CTA
#define MP   20          // padded row-stride (floats) in transposed smem buffers
#define MPB  (MP * 4)    // 80 bytes
#define KB   32          // k-block size for weight staging
#define NB   (CDIM / KB) // 8 blocks

// smem byte offsets for ODE kernel
#define OFF_YS   0
#define OFF_K1   20480
#define OFF_K2   40960
#define OFF_K3   61440
#define OFF_ARGS 81920
#define OFF_H1   102400
#define OFF_WB0  122880
#define OFF_WB1  155648
#define OFF_RED  188416
#define ODE_SMEM 188928

typedef unsigned long long U64;

// ---------------------------------------------------------------------------
// Scratch (device globals: no allocation allowed)
// ---------------------------------------------------------------------------
__device__ float g_qbuf[3 * BDIM * HEADS * NTOK * HD]; // [3][B][H][N][hd]
__device__ float g_attnout[ROWS * CDIM];               // attention concat [B*N][C]
__device__ float g_x1[ROWS * CDIM];                    // x1 = LN(x + attn)
__device__ float g_ode[ROWS * CDIM];                   // ODE output at lead time

// ---------------------------------------------------------------------------
// packed f32x2 helpers (Blackwell FFMA2 path)
// ---------------------------------------------------------------------------
__device__ __forceinline__ U64 pack2(float lo, float hi) {
    U64 r; asm("mov.b64 %0, {%1, %2};" : "=l"(r) : "f"(lo), "f"(hi)); return r;
}
__device__ __forceinline__ void unpack2(U64 v, float& lo, float& hi) {
    asm("mov.b64 {%0, %1}, %2;" : "=f"(lo), "=f"(hi) : "l"(v));
}
__device__ __forceinline__ U64 fma2(U64 a, U64 b, U64 c) {
    U64 d; asm("fma.rn.f32x2 %0, %1, %2, %3;" : "=l"(d) : "l"(a), "l"(b), "l"(c)); return d;
}
__device__ __forceinline__ U64 add2(U64 a, U64 b) {
    U64 d; asm("add.rn.f32x2 %0, %1, %2;" : "=l"(d) : "l"(a), "l"(b)); return d;
}
__device__ __forceinline__ U64 mul2(U64 a, U64 b) {
    U64 d; asm("mul.rn.f32x2 %0, %1, %2;" : "=l"(d) : "l"(a), "l"(b)); return d;
}
__device__ __forceinline__ void lds2x64(uint32_t addr, U64& a, U64& b) {
    asm volatile("ld.shared.v2.b64 {%0, %1}, [%2];" : "=l"(a), "=l"(b) : "r"(addr));
}
__device__ __forceinline__ void lds4f(uint32_t addr, float& x, float& y, float& z, float& w) {
    asm volatile("ld.shared.v4.f32 {%0, %1, %2, %3}, [%4];"
                 : "=f"(x), "=f"(y), "=f"(z), "=f"(w) : "r"(addr));
}
__device__ __forceinline__ void sts2x64(uint32_t addr, U64 a, U64 b) {
    asm volatile("st.shared.v2.b64 [%0], {%1, %2};" :: "r"(addr), "l"(a), "l"(b));
}
__device__ __forceinline__ void sts4f(uint32_t addr, float x, float y, float z, float w) {
    asm volatile("st.shared.v4.f32 [%0], {%1, %2, %3, %4};"
                 :: "r"(addr), "f"(x), "f"(y), "f"(z), "f"(w));
}
__device__ __forceinline__ void cp_async16(uint32_t sdst, const void* gsrc) {
    asm volatile("cp.async.cg.shared.global [%0], [%1], 16;" :: "r"(sdst), "l"(gsrc));
}
__device__ __forceinline__ void cp_commit() { asm volatile("cp.async.commit_group;"); }
__device__ __forceinline__ void cp_wait_all() { asm volatile("cp.async.wait_group 0;" ::: "memory"); }

// ---------------------------------------------------------------------------
// K1: qkv = x @ wqkv + bqkv, scattered into [3][B][H][N][hd]
// ---------------------------------------------------------------------------
__global__ void qkv_kernel(const float* __restrict__ x,
                           const float* __restrict__ wqkv,
                           const float* __restrict__ bqkv) {
    __shared__ __align__(16) float As[CDIM * 36];
    int tid = threadIdx.x, cg = tid & 31, rg = tid >> 5;
    int r0 = blockIdx.x * 32;
    int cb = blockIdx.y;

    for (int idx = tid; idx < 32 * CDIM; idx += 256) {
        int c = idx & 255, m = idx >> 8;
        As[c * 36 + m] = x[(r0 + m) * CDIM + c];
    }
    __syncthreads();

    float acc[4][8];
#pragma unroll
    for (int j = 0; j < 8; j++) {
        float bv = bqkv[cb * 256 + cg + 32 * j];
#pragma unroll
        for (int mm = 0; mm < 4; mm++) acc[mm][j] = bv;
    }
    int m0 = rg * 4;
    const float* wp = wqkv + cb * 256 + cg;
#pragma unroll 4
    for (int k = 0; k < CDIM; k++) {
        float4 av = *(const float4*)(As + k * 36 + m0);
#pragma unroll
        for (int j = 0; j < 8; j++) {
            float w = wp[k * 768 + 32 * j];
            acc[0][j] = fmaf(av.x, w, acc[0][j]);
            acc[1][j] = fmaf(av.y, w, acc[1][j]);
            acc[2][j] = fmaf(av.z, w, acc[2][j]);
            acc[3][j] = fmaf(av.w, w, acc[3][j]);
        }
    }
#pragma unroll
    for (int mm = 0; mm < 4; mm++) {
        int r = r0 + m0 + mm;
        int b = r >> 8, n = r & 255;
#pragma unroll
        for (int j = 0; j < 8; j++) {
            int cl = cg + 32 * j;
            int h = cl >> 5, d = cl & 31;
            g_qbuf[(((cb * BDIM + b) * HEADS + h) * NTOK + n) * HD + d] = acc[mm][j];
        }
    }
}

// ---------------------------------------------------------------------------
// K2: per-(b,h) softmax attention
// ---------------------------------------------------------------------------
#define ATTN_SMEM ((3 * 256 * 33 + 8 * 256) * 4)

__global__ void attn_kernel() {
    extern __shared__ float sm[];
    float* qs = sm;
    float* ks = qs + 256 * 33;
    float* vs = ks + 256 * 33;
    float* prob = vs + 256 * 33;

    int tid = threadIdx.x, lane = tid & 31, w = tid >> 5;
    int bh = blockIdx.x, b = bh >> 3, h = bh & 7;
    const float scale = 0.17677669529663687f;

    const float* qg = g_qbuf + ((0 * BDIM + b) * HEADS + h) * NTOK * HD;
    const float* kg = g_qbuf + ((1 * BDIM + b) * HEADS + h) * NTOK * HD;
    const float* vg = g_qbuf + ((2 * BDIM + b) * HEADS + h) * NTOK * HD;
    for (int idx = tid; idx < NTOK * HD; idx += 256) {
        int n = idx >> 5, d = idx & 31;
        qs[n * 33 + d] = qg[idx] * scale;
        ks[n * 33 + d] = kg[idx];
        vs[n * 33 + d] = vg[idx];
    }
    __syncthreads();

    for (int n = w; n < NTOK; n += 8) {
        float s[8];
#pragma unroll
        for (int u = 0; u < 8; u++) {
            int j = lane + 32 * u;
            float a = 0.f;
#pragma unroll 8
            for (int d = 0; d < HD; d++) a = fmaf(qs[n * 33 + d], ks[j * 33 + d], a);
            s[u] = a;
        }
        float mx = s[0];
#pragma unroll
        for (int u = 1; u < 8; u++) mx = fmaxf(mx, s[u]);
#pragma unroll
        for (int o = 16; o > 0; o >>= 1) mx = fmaxf(mx, __shfl_xor_sync(0xffffffffu, mx, o));
        float sum = 0.f;
#pragma unroll
        for (int u = 0; u < 8; u++) { s[u] = __expf(s[u] - mx); sum += s[u]; }
#pragma unroll
        for (int o = 16; o > 0; o >>= 1) sum += __shfl_xor_sync(0xffffffffu, sum, o);
        float inv = 1.f / sum;
#pragma unroll
        for (int u = 0; u < 8; u++) prob[w * 256 + lane + 32 * u] = s[u] * inv;
        __syncwarp();
        float acc = 0.f;
#pragma unroll 8
        for (int j = 0; j < NTOK; j++) acc = fmaf(prob[w * 256 + j], vs[j * 33 + lane], acc);
        g_attnout[(b * NTOK + n) * CDIM + h * HD + lane] = acc;
        __syncwarp();
    }
}

// ---------------------------------------------------------------------------
// K3: x1 = LN(x + attnout @ wo + bo; g1,b1)
// ---------------------------------------------------------------------------
__global__ void proj_ln_kernel(const float* __restrict__ x,
                               const float* __restrict__ wo,
                               const float* __restrict__ bo,
                               const float* __restrict__ g1,
                               const float* __restrict__ b1) {
    __shared__ __align__(16) float As[CDIM * 36];
    int tid = threadIdx.x, cg = tid & 31, rg = tid >> 5;
    int r0 = blockIdx.x * 32;
    for (int idx = tid; idx < 32 * CDIM; idx += 256) {
        int c = idx & 255, m = idx >> 8;
        As[c * 36 + m] = g_attnout[(r0 + m) * CDIM + c];
    }
    __syncthreads();

    float acc[4][8];
#pragma unroll
    for (int j = 0; j < 8; j++) {
        float bv = bo[cg + 32 * j];
#pragma unroll
        for (int mm = 0; mm < 4; mm++) acc[mm][j] = bv;
    }
    int m0 = rg * 4;
    const float* wp = wo + cg;
#pragma unroll 4
    for (int k = 0; k < CDIM; k++) {
        float4 av = *(const float4*)(As + k * 36 + m0);
#pragma unroll
        for (int j = 0; j < 8; j++) {
            float w = wp[k * CDIM + 32 * j];
            acc[0][j] = fmaf(av.x, w, acc[0][j]);
            acc[1][j] = fmaf(av.y, w, acc[1][j]);
            acc[2][j] = fmaf(av.z, w, acc[2][j]);
            acc[3][j] = fmaf(av.w, w, acc[3][j]);
        }
    }
#pragma unroll
    for (int mm = 0; mm < 4; mm++) {
        int r = r0 + m0 + mm;
#pragma unroll
        for (int j = 0; j < 8; j++) acc[mm][j] += x[r * CDIM + cg + 32 * j];
        float ls = 0.f, lq = 0.f;
#pragma unroll
        for (int j = 0; j < 8; j++) { ls += acc[mm][j]; lq += acc[mm][j] * acc[mm][j]; }
#pragma unroll
        for (int o = 16; o > 0; o >>= 1) {
            ls += __shfl_xor_sync(0xffffffffu, ls, o);
            lq += __shfl_xor_sync(0xffffffffu, lq, o);
        }
        float mean = ls * (1.f / 256.f);
        float var  = lq * (1.f / 256.f) - mean * mean;
        float rstd = rsqrtf(var + EPSLN);
#pragma unroll
        for (int j = 0; j < 8; j++) {
            int c = cg + 32 * j;
            g_x1[r * CDIM + c] = (acc[mm][j] - mean) * rstd * g1[c] + b1[c];
        }
    }
}

// ---------------------------------------------------------------------------
// K4: persistent ODE kernel. 128 CTAs x 256 threads; 16 rows/CTA.
// f32x2 packed FMA; weights staged in smem via cp.async double-buffer.
// Thread tile: 4 rows (packed in 2 x f32x2) x 4 contiguous cols.
//   cg = tid & 63 -> cols 4*cg..4*cg+3 ; rg = tid >> 6 -> rows 4*rg..4*rg+3
//   warps (2*rg, 2*rg+1) cover cols 0-127 / 128-255 of rows 4rg..4rg+3.
// ---------------------------------------------------------------------------
__device__ __forceinline__ void prefetch_w(uint32_t sdst, const float* gsrc, int tid) {
#pragma unroll
    for (int i = 0; i < (KB * CDIM * 4) / (256 * 16); i++) {   // 8 x 16B per thread
        int off = (tid + i * 256) * 16;
        cp_async16(sdst + off, (const char*)gsrc + off);
    }
    cp_commit();
}

// GEMM: acc[c][p] (c=0..3 cols, p=0..1 row-pairs) = bias + src^T @ W(tile cols)
__device__ __forceinline__ void gemm_tile(uint32_t sbase, uint32_t srcOff,
                                          const float* __restrict__ gw,
                                          const U64* bias, U64 acc[4][2],
                                          int tid, int rg, int cg) {
    prefetch_w(sbase + OFF_WB0, gw, tid);
#pragma unroll
    for (int c = 0; c < 4; c++) { acc[c][0] = bias[c]; acc[c][1] = bias[c]; }
    uint32_t aBase = sbase + srcOff + rg * 16;   // + k*80
    uint32_t wCol  = cg * 16;                    // + kk*1024
    for (int kb = 0; kb < NB; kb++) {
        cp_wait_all();
        __syncthreads();
        if (kb < NB - 1)
            prefetch_w(sbase + ((kb & 1) ? OFF_WB0 : OFF_WB1), gw + (kb + 1) * KB * CDIM, tid);
        uint32_t wb = sbase + ((kb & 1) ? OFF_WB1 : OFF_WB0) + wCol;
        uint32_t aK = aBase + kb * KB * MPB;
        for (int kk2 = 0; kk2 < 2; kk2++) {
#pragma unroll
            for (int kk = 0; kk < 16; kk++) {
                int kl = kk2 * 16 + kk;
                U64 aL, aH;
                lds2x64(aK + kl * MPB, aL, aH);
                float wx, wy, wz, ww;
                lds4f(wb + kl * (CDIM * 4), wx, wy, wz, ww);
                U64 w0 = pack2(wx, wx), w1 = pack2(wy, wy);
                U64 w2 = pack2(wz, wz), w3 = pack2(ww, ww);
                acc[0][0] = fma2(aL, w0, acc[0][0]); acc[0][1] = fma2(aH, w0, acc[0][1]);
                acc[1][0] = fma2(aL, w1, acc[1][0]); acc[1][1] = fma2(aH, w1, acc[1][1]);
                acc[2][0] = fma2(aL, w2, acc[2][0]); acc[2][1] = fma2(aH, w2, acc[2][1]);
                acc[3][0] = fma2(aL, w3, acc[3][0]); acc[3][1] = fma2(aH, w3, acc[3][1]);
            }
        }
    }
}

__global__ void __launch_bounds__(256, 1)
ode_kernel(const int* __restrict__ lead_times, const int* __restrict__ nsp,
           const float* __restrict__ wl1, const float* __restrict__ bl1,
           const float* __restrict__ wl2, const float* __restrict__ bl2,
           const float* __restrict__ gn, const float* __restrict__ bn) {
    extern __shared__ __align__(16) float sm[];
    uint32_t sbase = (uint32_t)__cvta_generic_to_shared(sm);
    float* red = sm + OFF_RED / 4;   // [16 rows][2 halves] sums, then sqsums at +64

    int tid = threadIdx.x;
    int cg = tid & 63, rg = tid >> 6;
    int lane = tid & 31, warp = tid >> 5, half = warp & 1;
    int r0 = blockIdx.x * MROW;
    int steps = lead_times[r0 >> 8];
    int ns = nsp ? nsp[0] : 50;
    if (steps > ns) steps = ns;
    if (steps < 0) steps = 0;

    // preload per-thread packed constants (cols 4cg..4cg+3)
    U64 bl1p[4], bl2p[4], gnp[4], bnp[4];
    {
        float4 v1 = *(const float4*)(bl1 + 4 * cg);
        float4 v2 = *(const float4*)(bl2 + 4 * cg);
        float4 vg = *(const float4*)(gn  + 4 * cg);
        float4 vb = *(const float4*)(bn  + 4 * cg);
        bl1p[0] = pack2(v1.x, v1.x); bl1p[1] = pack2(v1.y, v1.y);
        bl1p[2] = pack2(v1.z, v1.z); bl1p[3] = pack2(v1.w, v1.w);
        bl2p[0] = pack2(v2.x, v2.x); bl2p[1] = pack2(v2.y, v2.y);
        bl2p[2] = pack2(v2.z, v2.z); bl2p[3] = pack2(v2.w, v2.w);
        gnp[0] = pack2(vg.x, vg.x); gnp[1] = pack2(vg.y, vg.y);
        gnp[2] = pack2(vg.z, vg.z); gnp[3] = pack2(vg.w, vg.w);
        bnp[0] = pack2(vb.x, vb.x); bnp[1] = pack2(vb.y, vb.y);
        bnp[2] = pack2(vb.z, vb.z); bnp[3] = pack2(vb.w, vb.w);
    }
    const U64 THREE = pack2(3.f, 3.f);
    const U64 DT8   = pack2(DT * 0.125f, DT * 0.125f);

    // load x1 -> ys (transposed [c][m])
    for (int idx = tid; idx < MROW * CDIM; idx += 256) {
        int c = idx & 255, m = idx >> 8;
        sm[OFF_YS / 4 + c * MP + m] = g_x1[(r0 + m) * CDIM + c];
    }
    __syncthreads();

    // per-thread epilogue addresses (byte offsets into transposed buffers)
    uint32_t tileOff = (uint32_t)(4 * cg) * MPB + (uint32_t)rg * 16; // (+c*MPB per col)

    for (int s = 0; s < steps; s++) {
        for (int st = 0; st < 4; st++) {
            uint32_t srcOff = (st == 0) ? OFF_YS : OFF_ARGS;
            uint32_t dstOff = (st == 0) ? OFF_K1 : (st == 1) ? OFF_K2
                             : (st == 2) ? OFF_K3 : OFF_YS;
            bool fin = (st == 3);

            U64 acc[4][2];
            // ---- GEMM1: h1 = relu(src @ wl1 + bl1) ----
            gemm_tile(sbase, srcOff, wl1, bl1p, acc, tid, rg, cg);
#pragma unroll
            for (int c = 0; c < 4; c++) {
                float f0, f1, f2, f3;
                unpack2(acc[c][0], f0, f1); unpack2(acc[c][1], f2, f3);
                sts4f(sbase + OFF_H1 + tileOff + c * MPB,
                      fmaxf(f0, 0.f), fmaxf(f1, 0.f), fmaxf(f2, 0.f), fmaxf(f3, 0.f));
            }
            // (h1 stores are published by the first __syncthreads inside gemm_tile)

            // ---- GEMM2: h2 = h1 @ wl2 + bl2 ----
            gemm_tile(sbase, OFF_H1, wl2, bl2p, acc, tid, rg, cg);

            // ---- residual + LN ----
#pragma unroll
            for (int c = 0; c < 4; c++) {
                U64 rA, rB;
                lds2x64(sbase + srcOff + tileOff + c * MPB, rA, rB);
                acc[c][0] = add2(acc[c][0], rA);
                acc[c][1] = add2(acc[c][1], rB);
            }
            U64 S0 = acc[0][0], S1 = acc[0][1];
            U64 Q0 = mul2(acc[0][0], acc[0][0]), Q1 = mul2(acc[0][1], acc[0][1]);
#pragma unroll
            for (int c = 1; c < 4; c++) {
                S0 = add2(S0, acc[c][0]); S1 = add2(S1, acc[c][1]);
                Q0 = fma2(acc[c][0], acc[c][0], Q0);
                Q1 = fma2(acc[c][1], acc[c][1], Q1);
            }
            float s0, s1, s2, s3, q0, q1, q2, q3;
            unpack2(S0, s0, s1); unpack2(S1, s2, s3);
            unpack2(Q0, q0, q1); unpack2(Q1, q2, q3);
#pragma unroll
            for (int o = 16; o > 0; o >>= 1) {
                s0 += __shfl_xor_sync(0xffffffffu, s0, o);
                s1 += __shfl_xor_sync(0xffffffffu, s1, o);
                s2 += __shfl_xor_sync(0xffffffffu, s2, o);
                s3 += __shfl_xor_sync(0xffffffffu, s3, o);
                q0 += __shfl_xor_sync(0xffffffffu, q0, o);
                q1 += __shfl_xor_sync(0xffffffffu, q1, o);
                q2 += __shfl_xor_sync(0xffffffffu, q2, o);
                q3 += __shfl_xor_sync(0xffffffffu, q3, o);
            }
            if (lane == 0) {
                int m0 = rg * 4;
                red[(m0 + 0) * 2 + half] = s0;
                red[(m0 + 1) * 2 + half] = s1;
                red[(m0 + 2) * 2 + half] = s2;
                red[(m0 + 3) * 2 + half] = s3;
                red[64 + (m0 + 0) * 2 + half] = q0;
                red[64 + (m0 + 1) * 2 + half] = q1;
                red[64 + (m0 + 2) * 2 + half] = q2;
                red[64 + (m0 + 3) * 2 + half] = q3;
            }
            __syncthreads();
            float A[4], Bv[4];
#pragma unroll
            for (int r = 0; r < 4; r++) {
                int m = rg * 4 + r;
                float ts = red[m * 2] + red[m * 2 + 1];
                float tq = red[64 + m * 2] + red[64 + m * 2 + 1];
                float mean = ts * (1.f / 256.f);
                float var  = tq * (1.f / 256.f) - mean * mean;
                float rstd = rsqrtf(var + EPSLN);
                A[r] = rstd; Bv[r] = -mean * rstd;
            }
            U64 Ap0 = pack2(A[0], A[1]), Ap1 = pack2(A[2], A[3]);
            U64 Bp0 = pack2(Bv[0], Bv[1]), Bp1 = pack2(Bv[2], Bv[3]);
            __syncthreads();  // red free for reuse before anyone rewrites it
#pragma unroll
            for (int c = 0; c < 4; c++) {
                U64 n0 = fma2(acc[c][0], Ap0, Bp0);
                U64 n1 = fma2(acc[c][1], Ap1, Bp1);
                U64 kv0 = fma2(n0, gnp[c], bnp[c]);
                U64 kv1 = fma2(n1, gnp[c], bnp[c]);
                uint32_t off = tileOff + c * MPB;
                if (!fin) {
                    sts2x64(sbase + dstOff + off, kv0, kv1);
                } else {
                    U64 k1a, k1b, k2a, k2b, k3a, k3b, ya, yb;
                    lds2x64(sbase + OFF_K1 + off, k1a, k1b);
                    lds2x64(sbase + OFF_K2 + off, k2a, k2b);
                    lds2x64(sbase + OFF_K3 + off, k3a, k3b);
                    lds2x64(sbase + OFF_YS + off, ya, yb);
                    U64 t0 = add2(k2a, k3a), t1 = add2(k2b, k3b);
                    t0 = fma2(t0, THREE, k1a); t1 = fma2(t1, THREE, k1b);
                    t0 = add2(t0, kv0); t1 = add2(t1, kv1);
                    ya = fma2(t0, DT8, ya); yb = fma2(t1, DT8, yb);
                    sts2x64(sbase + OFF_YS + off, ya, yb);
                }
            }
            __syncthreads();

            // ---- build args for next stage ----
            if (st < 3) {
                int c = tid;             // one column per thread
                uint32_t base = (uint32_t)c * MPB;
#pragma unroll
                for (int i = 0; i < 4; i++) {
                    uint32_t o = base + i * 16;
                    float4 yv, k1v, k2v, k3v, av;
                    lds4f(sbase + OFF_YS + o, yv.x, yv.y, yv.z, yv.w);
                    lds4f(sbase + OFF_K1 + o, k1v.x, k1v.y, k1v.z, k1v.w);
                    if (st == 0) {
                        const float cdt = DT * (1.f / 3.f);
                        av.x = yv.x + cdt * k1v.x; av.y = yv.y + cdt * k1v.y;
                        av.z = yv.z + cdt * k1v.z; av.w = yv.w + cdt * k1v.w;
                    } else if (st == 1) {
                        lds4f(sbase + OFF_K2 + o, k2v.x, k2v.y, k2v.z, k2v.w);
                        av.x = yv.x + DT * (k2v.x - (1.f / 3.f) * k1v.x);
                        av.y = yv.y + DT * (k2v.y - (1.f / 3.f) * k1v.y);
                        av.z = yv.z + DT * (k2v.z - (1.f / 3.f) * k1v.z);
                        av.w = yv.w + DT * (k2v.w - (1.f / 3.f) * k1v.w);
                    } else {
                        lds4f(sbase + OFF_K2 + o, k2v.x, k2v.y, k2v.z, k2v.w);
                        lds4f(sbase + OFF_K3 + o, k3v.x, k3v.y, k3v.z, k3v.w);
                        av.x = yv.x + DT * (k1v.x - k2v.x + k3v.x);
                        av.y = yv.y + DT * (k1v.y - k2v.y + k3v.y);
                        av.z = yv.z + DT * (k1v.z - k2v.z + k3v.z);
                        av.w = yv.w + DT * (k1v.w - k2v.w + k3v.w);
                    }
                    sts4f(sbase + OFF_ARGS + o, av.x, av.y, av.z, av.w);
                }
                // args published by first __syncthreads inside next gemm_tile
            }
        }
    }

    for (int idx = tid; idx < MROW * CDIM; idx += 256) {
        int c = idx & 255, m = idx >> 8;
        g_ode[(r0 + m) * CDIM + c] = sm[OFF_YS / 4 + c * MP + m];
    }
}

// ---------------------------------------------------------------------------
// K5: out = LN(x1 + ode; g2,b2)
// ---------------------------------------------------------------------------
__global__ void final_ln_kernel(const float* __restrict__ g2,
                                const float* __restrict__ b2,
                                float* __restrict__ out) {
    int tid = threadIdx.x, lane = tid & 31, w = tid >> 5;
    int r = blockIdx.x * 8 + w;
    float v[8], ls = 0.f, lq = 0.f;
#pragma unroll
    for (int u = 0; u < 8; u++) {
        int c = lane + 32 * u;
        float t = g_x1[r * CDIM + c] + g_ode[r * CDIM + c];
        v[u] = t; ls += t; lq += t * t;
    }
#pragma unroll
    for (int o = 16; o > 0; o >>= 1) {
        ls += __shfl_xor_sync(0xffffffffu, ls, o);
        lq += __shfl_xor_sync(0xffffffffu, lq, o);
    }
    float mean = ls * (1.f / 256.f);
    float var  = lq * (1.f / 256.f) - mean * mean;
    float rstd = rsqrtf(var + EPSLN);
#pragma unroll
    for (int u = 0; u < 8; u++) {
        int c = lane + 32 * u;
        out[r * CDIM + c] = (v[u] - mean) * rstd * g2[c] + b2[c];
    }
}

// ---------------------------------------------------------------------------
// Launch
// ---------------------------------------------------------------------------
extern "C" void kernel_launch(void* const* d_in, const int* in_sizes, int n_in,
                              void* d_out, int out_size) {
    const float* x    = (const float*)d_in[0];
    const float* wqkv = (const float*)d_in[1];
    const float* bqkv = (const float*)d_in[2];
    const float* wo   = (const float*)d_in[3];
    const float* bo   = (const float*)d_in[4];
    const float* g1   = (const float*)d_in[5];
    const float* b1   = (const float*)d_in[6];
    const float* g2   = (const float*)d_in[7];
    const float* b2   = (const float*)d_in[8];
    const float* wl1  = (const float*)d_in[9];
    const float* bl1  = (const float*)d_in[10];
    const float* wl2  = (const float*)d_in[11];
    const float* bl2  = (const float*)d_in[12];
    const float* gn   = (const float*)d_in[13];
    const float* bn   = (const float*)d_in[14];
    const int* lead   = (const int*)d_in[15];
    const int* nsteps = (n_in > 16) ? (const int*)d_in[16] : nullptr;
    float* out = (float*)d_out;

    cudaFuncSetAttribute(attn_kernel, cudaFuncAttributeMaxDynamicSharedMemorySize, ATTN_SMEM);
    cudaFuncSetAttribute(ode_kernel, cudaFuncAttributeMaxDynamicSharedMemorySize, ODE_SMEM);

    qkv_kernel<<<dim3(64, 3), 256>>>(x, wqkv, bqkv);
    attn_kernel<<<64, 256, ATTN_SMEM>>>();
    proj_ln_kernel<<<64, 256>>>(x, wo, bo, g1, b1);
    ode_kernel<<<128, 256, ODE_SMEM>>>(lead, nsteps, wl1, bl1, wl2, bl2, gn, bn);
    final_ln_kernel<<<256, 256>>>(g2, b2, out);
}